// round 12
// baseline (speedup 1.0000x reference)
#include <cuda_runtime.h>

#define N_NODES 50000
#define N_EDGES 800000
#define ET      (N_EDGES + N_NODES)   // 850000 edges incl self loops
#define HEADS   4
#define F12     128                    // 4*32
#define F3      188                    // 4*47
#define NCLS    47
#define NEG_SLOPE 0.2f

// ---------------- scratch (device globals, no allocation) ----------------
// g_deg/g_flag/g_carry zero at module load; re-zeroed in finalize3 tail.
__device__ float g_h[N_NODES * F3];        // linear output of current layer
__device__ float g_buf[N_NODES * F12];     // activations between layers
__device__ float g_agg[N_NODES * F3];      // layer-3 aggregation (pre-mean)
__device__ float g_asrc[N_NODES * HEADS];
__device__ float g_adst[N_NODES * HEADS];
__device__ int g_deg[N_NODES];
__device__ int g_rowptr[N_NODES + 1];
__device__ int g_cursor[N_NODES];
__device__ int g_col[ET];                  // src node per CSR slot
__device__ int g_carry[64];
__device__ int g_flag[64];

// ================= CSR build =================
__global__ void csr_hist_kernel(const int* __restrict__ ei) {
    int e = blockIdx.x * blockDim.x + threadIdx.x;
    if (e >= ET) return;
    int dst = (e < N_EDGES) ? ei[N_EDGES + e] : (e - N_EDGES);
    atomicAdd(&g_deg[dst], 1);
}

// single-kernel chained scan: 49 blocks x 1024; also zeroes g_cursor.
__global__ void csr_scan_kernel() {
    __shared__ int s[1024];
    __shared__ int s_carry;
    int b = blockIdx.x, t = threadIdx.x;
    int i = b * 1024 + t;
    if (i < N_NODES) g_cursor[i] = 0;
    int v = (i < N_NODES) ? g_deg[i] : 0;
    s[t] = v;
    __syncthreads();
#pragma unroll
    for (int off = 1; off < 1024; off <<= 1) {
        int x = (t >= off) ? s[t - off] : 0;
        __syncthreads();
        s[t] += x;
        __syncthreads();
    }
    int incl = s[t];
    int total = s[1023];
    if (t == 0) {
        int carry = 0;
        if (b > 0) {
            while (atomicAdd(&g_flag[b - 1], 0) == 0) { }
            carry = g_carry[b - 1];
        }
        s_carry = carry;
        g_carry[b] = carry + total;
        __threadfence();
        atomicExch(&g_flag[b], 1);
    }
    __syncthreads();
    int carry = s_carry;
    if (i <= N_NODES) g_rowptr[i] = carry + incl - v;   // exclusive prefix
}

__global__ void csr_scatter_kernel(const int* __restrict__ ei) {
    int e = blockIdx.x * blockDim.x + threadIdx.x;
    if (e >= ET) return;
    int src, dst;
    if (e < N_EDGES) { src = ei[e]; dst = ei[N_EDGES + e]; }
    else             { src = dst = e - N_EDGES; }
    int pos = atomicAdd(&g_cursor[dst], 1);
    g_col[g_rowptr[dst] + pos] = src;
}

// ================= register-tiled GEMM: g_h = x @ W =================
// 64 nodes x (32*TN) feats per block, 256 threads, 8x TN micro-tile.
// ft = tid&31 owns feats [ft*TN, ft*TN+TN); nt = tid>>5 owns nodes nt*8..+8.
template <int TN, int FOUT_REAL>
__global__ __launch_bounds__(256) void gemm_tile_kernel(const float* __restrict__ x,
                                                        const float* __restrict__ W) {
    const int FOUT_PAD = 32 * TN;
    __shared__ float ws[32][FOUT_PAD];
    __shared__ float xs[64][36];
    int tid = threadIdx.x;
    int ft = tid & 31;
    int nt = tid >> 5;
    int n0 = blockIdx.x * 64;

    float acc[8][TN];
#pragma unroll
    for (int i = 0; i < 8; i++)
#pragma unroll
        for (int j = 0; j < TN; j++) acc[i][j] = 0.f;

    for (int kt = 0; kt < 128; kt += 32) {
        // x tile: 64x32 = 512 float4 loads
#pragma unroll
        for (int idx = tid; idx < 512; idx += 256) {
            int r = idx >> 3, c4 = idx & 7;
            int n = n0 + r;
            float4 v = (n < N_NODES) ? *(const float4*)&x[n * 128 + kt + c4 * 4]
                                     : make_float4(0.f, 0.f, 0.f, 0.f);
            *(float4*)&xs[r][c4 * 4] = v;
        }
        // W tile: 32 x FOUT_PAD
        const int NF4 = FOUT_PAD / 4;
        for (int idx = tid; idx < 32 * NF4; idx += 256) {
            int r = idx / NF4, c4 = idx % NF4;
            int col = c4 * 4;
            float4 v = (col + 3 < FOUT_REAL)
                           ? *(const float4*)&W[(kt + r) * FOUT_REAL + col]
                           : make_float4(0.f, 0.f, 0.f, 0.f);
            *(float4*)&ws[r][col] = v;
        }
        __syncthreads();
#pragma unroll
        for (int kk = 0; kk < 32; kk++) {
            float xv[8];
#pragma unroll
            for (int i = 0; i < 8; i++) xv[i] = xs[nt * 8 + i][kk];
            float wv[TN];
            if (TN == 4) {
                float4 w4 = *(const float4*)&ws[kk][ft * 4];
                wv[0] = w4.x; wv[1] = w4.y; wv[2] = w4.z; wv[3] = w4.w;
            } else {
#pragma unroll
                for (int j = 0; j < TN; j += 2) {
                    float2 w2 = *(const float2*)&ws[kk][ft * TN + j];
                    wv[j] = w2.x; wv[j + 1] = w2.y;
                }
            }
#pragma unroll
            for (int i = 0; i < 8; i++)
#pragma unroll
                for (int j = 0; j < TN; j++)
                    acc[i][j] = fmaf(xv[i], wv[j], acc[i][j]);
        }
        __syncthreads();
    }
#pragma unroll
    for (int i = 0; i < 8; i++) {
        int n = n0 + nt * 8 + i;
        if (n < N_NODES) {
            if (TN == 4) {
                *(float4*)&g_h[n * FOUT_REAL + ft * 4] =
                    make_float4(acc[i][0], acc[i][1], acc[i][2], acc[i][3]);
            } else {
#pragma unroll
                for (int j = 0; j < TN; j++) {
                    int f = ft * TN + j;
                    if (f < FOUT_REAL) g_h[n * FOUT_REAL + f] = acc[i][j];
                }
            }
        }
    }
}

// ================= attention coefficients (warp per node) =================
__global__ void attn_coef128_kernel(const float* __restrict__ as,
                                    const float* __restrict__ ad) {
    int gtid = blockIdx.x * blockDim.x + threadIdx.x;
    int n = gtid >> 5;
    int lane = gtid & 31;
    if (n >= N_NODES) return;
    float4 v  = *(const float4*)&g_h[n * F12 + 4 * lane];
    float4 a4 = *(const float4*)&as[4 * lane];
    float4 d4 = *(const float4*)&ad[4 * lane];
    float ps = v.x * a4.x + v.y * a4.y + v.z * a4.z + v.w * a4.w;
    float pd = v.x * d4.x + v.y * d4.y + v.z * d4.z + v.w * d4.w;
    ps += __shfl_xor_sync(0xFFFFFFFFu, ps, 1);
    pd += __shfl_xor_sync(0xFFFFFFFFu, pd, 1);
    ps += __shfl_xor_sync(0xFFFFFFFFu, ps, 2);
    pd += __shfl_xor_sync(0xFFFFFFFFu, pd, 2);
    ps += __shfl_xor_sync(0xFFFFFFFFu, ps, 4);
    pd += __shfl_xor_sync(0xFFFFFFFFu, pd, 4);
    if ((lane & 7) == 0) {
        g_asrc[n * HEADS + (lane >> 3)] = ps;
        g_adst[n * HEADS + (lane >> 3)] = pd;
    }
}

__global__ void attn_coef188_kernel(const float* __restrict__ as,
                                    const float* __restrict__ ad) {
    int gtid = blockIdx.x * blockDim.x + threadIdx.x;
    int n = gtid >> 5;
    int lane = gtid & 31;
    if (n >= N_NODES) return;
    float hs[HEADS] = {0.f, 0.f, 0.f, 0.f};
    float hd[HEADS] = {0.f, 0.f, 0.f, 0.f};
#pragma unroll
    for (int k = 0; k < 6; k++) {
        int f = lane + 32 * k;
        if (f < F3) {
            float v = g_h[n * F3 + f];
            int hh = f / NCLS;
            hs[hh] = fmaf(v, as[f], hs[hh]);
            hd[hh] = fmaf(v, ad[f], hd[hh]);
        }
    }
#pragma unroll
    for (int h = 0; h < HEADS; h++) {
#pragma unroll
        for (int o = 16; o > 0; o >>= 1) {
            hs[h] += __shfl_xor_sync(0xFFFFFFFFu, hs[h], o);
            hd[h] += __shfl_xor_sync(0xFFFFFFFFu, hd[h], o);
        }
    }
    if (lane < HEADS) {
        g_asrc[n * HEADS + lane] = hs[lane];
        g_adst[n * HEADS + lane] = hd[lane];
    }
}

// ================= fused softmax + gather-aggregate (no-max) =================
// softmax is shift-invariant; alpha is bounded (|alpha| small), so exp(alpha)
// directly — removes the rescale dependency chain entirely.
// warp per dst node; lane owns feats [4*lane,4*lane+4), head hh = lane>>3.
__global__ void gat_agg128_kernel(const float* __restrict__ bias) {
    int gtid = blockIdx.x * blockDim.x + threadIdx.x;
    int n = gtid >> 5;
    int lane = gtid & 31;
    if (n >= N_NODES) return;
    int beg = g_rowptr[n];
    int deg = g_rowptr[n + 1] - beg;
    int hh = lane >> 3;
    const float4 adst4 = *(const float4*)&g_adst[n * HEADS];
    float adst_h = (hh == 0) ? adst4.x : (hh == 1) ? adst4.y : (hh == 2) ? adst4.z : adst4.w;

    float den = 0.f;
    float4 acc = make_float4(0.f, 0.f, 0.f, 0.f);
#pragma unroll 4
    for (int i = 0; i < deg; i++) {
        int src = g_col[beg + i];
        float4 s4 = *(const float4*)&g_asrc[src * HEADS];   // broadcast across warp
        float a = ((hh == 0) ? s4.x : (hh == 1) ? s4.y : (hh == 2) ? s4.z : s4.w) + adst_h;
        a = (a >= 0.f) ? a : NEG_SLOPE * a;
        float e = __expf(a);
        den += e;
        float4 v = *(const float4*)&g_h[src * F12 + 4 * lane];
        acc.x = fmaf(v.x, e, acc.x);
        acc.y = fmaf(v.y, e, acc.y);
        acc.z = fmaf(v.z, e, acc.z);
        acc.w = fmaf(v.w, e, acc.w);
    }
    float idv = 1.f / den;
    float4 b4 = *(const float4*)&bias[4 * lane];
    float4 o;
    o.x = fmaxf(fmaf(acc.x, idv, b4.x), 0.f);
    o.y = fmaxf(fmaf(acc.y, idv, b4.y), 0.f);
    o.z = fmaxf(fmaf(acc.z, idv, b4.z), 0.f);
    o.w = fmaxf(fmaf(acc.w, idv, b4.w), 0.f);
    *(float4*)&g_buf[n * F12 + 4 * lane] = o;
}

// layer 3 variant: lane owns feats lane+32k (k<6) spanning multiple heads.
__global__ void gat_agg188_kernel() {
    int gtid = blockIdx.x * blockDim.x + threadIdx.x;
    int n = gtid >> 5;
    int lane = gtid & 31;
    if (n >= N_NODES) return;
    int beg = g_rowptr[n];
    int deg = g_rowptr[n + 1] - beg;
    const float4 adst4 = *(const float4*)&g_adst[n * HEADS];

    int hhk[6];
#pragma unroll
    for (int k = 0; k < 6; k++) hhk[k] = (lane + 32 * k) / NCLS;

    float den[HEADS] = {0.f, 0.f, 0.f, 0.f};
    float acc[6] = {0.f, 0.f, 0.f, 0.f, 0.f, 0.f};

#pragma unroll 2
    for (int i = 0; i < deg; i++) {
        int src = g_col[beg + i];
        float4 s4 = *(const float4*)&g_asrc[src * HEADS];
        float e[HEADS];
        {
            float a0 = s4.x + adst4.x; a0 = (a0 >= 0.f) ? a0 : NEG_SLOPE * a0;
            float a1 = s4.y + adst4.y; a1 = (a1 >= 0.f) ? a1 : NEG_SLOPE * a1;
            float a2 = s4.z + adst4.z; a2 = (a2 >= 0.f) ? a2 : NEG_SLOPE * a2;
            float a3 = s4.w + adst4.w; a3 = (a3 >= 0.f) ? a3 : NEG_SLOPE * a3;
            e[0] = __expf(a0); e[1] = __expf(a1); e[2] = __expf(a2); e[3] = __expf(a3);
        }
#pragma unroll
        for (int h = 0; h < HEADS; h++) den[h] += e[h];
        const float* hrow = &g_h[src * F3];
#pragma unroll
        for (int k = 0; k < 6; k++) {
            int f = lane + 32 * k;
            if (f < F3) acc[k] = fmaf(hrow[f], e[hhk[k]], acc[k]);
        }
    }
#pragma unroll
    for (int k = 0; k < 6; k++) {
        int f = lane + 32 * k;
        if (f < F3) g_agg[n * F3 + f] = acc[k] / den[hhk[k]];
    }
}

// ================= finalize layer 3: head mean + bias + log_softmax =================
// tail: re-zero g_deg / g_flag / g_carry for the next call.
__global__ void finalize3_kernel(const float* __restrict__ b3, float* __restrict__ out) {
    int gtid = blockIdx.x * blockDim.x + threadIdx.x;
    if (gtid < N_NODES) g_deg[gtid] = 0;
    if (gtid < 64) { g_flag[gtid] = 0; g_carry[gtid] = 0; }
    int n = gtid >> 5;
    int lane = gtid & 31;
    if (n >= N_NODES) return;
    int c0 = lane, c1 = lane + 32;
    float v0 = -1e30f, v1 = -1e30f;
    const float* row = &g_agg[n * F3];
    if (c0 < NCLS)
        v0 = 0.25f * (row[c0] + row[NCLS + c0] + row[2 * NCLS + c0] + row[3 * NCLS + c0]) + b3[c0];
    if (c1 < NCLS)
        v1 = 0.25f * (row[c1] + row[NCLS + c1] + row[2 * NCLS + c1] + row[3 * NCLS + c1]) + b3[c1];
    float mm = fmaxf(v0, v1);
#pragma unroll
    for (int o = 16; o > 0; o >>= 1) mm = fmaxf(mm, __shfl_xor_sync(0xFFFFFFFFu, mm, o));
    float s = 0.f;
    if (c0 < NCLS) s += expf(v0 - mm);
    if (c1 < NCLS) s += expf(v1 - mm);
#pragma unroll
    for (int o = 16; o > 0; o >>= 1) s += __shfl_xor_sync(0xFFFFFFFFu, s, o);
    float lse = mm + logf(s);
    if (c0 < NCLS) out[n * NCLS + c0] = v0 - lse;
    if (c1 < NCLS) out[n * NCLS + c1] = v1 - lse;
}

// ================= launch =================
extern "C" void kernel_launch(void* const* d_in, const int* in_sizes, int n_in,
                              void* d_out, int out_size) {
    const float* x   = (const float*)d_in[0];
    const int*   ei  = (const int*)d_in[1];   // edge_index is int32 (JAX x64 disabled)
    const float* W1  = (const float*)d_in[2];
    const float* a1s = (const float*)d_in[3];
    const float* a1d = (const float*)d_in[4];
    const float* b1  = (const float*)d_in[5];
    const float* W2  = (const float*)d_in[6];
    const float* a2s = (const float*)d_in[7];
    const float* a2d = (const float*)d_in[8];
    const float* b2  = (const float*)d_in[9];
    const float* W3  = (const float*)d_in[10];
    const float* a3s = (const float*)d_in[11];
    const float* a3d = (const float*)d_in[12];
    const float* b3  = (const float*)d_in[13];
    float* out = (float*)d_out;

    float* g_buf_ptr = nullptr;
    cudaGetSymbolAddress((void**)&g_buf_ptr, g_buf);

    int eb = (ET + 255) / 256;
    int gemm_blocks = (N_NODES + 63) / 64;       // 782
    int wb = (N_NODES * 32 + 255) / 256;

    // CSR build
    csr_hist_kernel<<<eb, 256>>>(ei);                          // launch 0
    csr_scan_kernel<<<49, 1024>>>();                           // launch 1
    csr_scatter_kernel<<<eb, 256>>>(ei);                       // launch 2
    // layer 1
    gemm_tile_kernel<4, 128><<<gemm_blocks, 256>>>(x, W1);     // launch 3 (profiled)
    attn_coef128_kernel<<<wb, 256>>>(a1s, a1d);
    gat_agg128_kernel<<<wb, 256>>>(b1);
    // layer 2
    gemm_tile_kernel<4, 128><<<gemm_blocks, 256>>>(g_buf_ptr, W2);
    attn_coef128_kernel<<<wb, 256>>>(a2s, a2d);
    gat_agg128_kernel<<<wb, 256>>>(b2);
    // layer 3
    gemm_tile_kernel<6, 188><<<gemm_blocks, 256>>>(g_buf_ptr, W3);
    attn_coef188_kernel<<<wb, 256>>>(a3s, a3d);
    gat_agg188_kernel<<<wb, 256>>>();
    finalize3_kernel<<<wb, 256>>>(b3, out);
}

// round 13
// speedup vs baseline: 1.0030x; 1.0030x over previous
#include <cuda_runtime.h>

#define N_NODES 50000
#define N_EDGES 800000
#define ET      (N_EDGES + N_NODES)   // 850000 edges incl self loops
#define HEADS   4
#define F12     128                    // 4*32
#define F3      188                    // 4*47
#define NCLS    47
#define NEG_SLOPE 0.2f

// ---------------- scratch (device globals, no allocation) ----------------
// g_deg/g_flag/g_carry zero at module load; re-zeroed in finalize3 tail.
__device__ float g_h[N_NODES * F3];        // linear output of current layer
__device__ float g_buf[N_NODES * F12];     // activations between layers
__device__ float g_agg[N_NODES * F3];      // layer-3 aggregation (pre-mean)
__device__ float g_asrc[N_NODES * HEADS];
__device__ float g_adst[N_NODES * HEADS];
__device__ int g_deg[N_NODES];
__device__ int g_rowptr[N_NODES + 1];
__device__ int g_cursor[N_NODES];
__device__ int g_col[ET];                  // src node per CSR slot
__device__ int g_carry[64];
__device__ int g_flag[64];

// ================= CSR build =================
__global__ void csr_hist_kernel(const int* __restrict__ ei) {
    int e = blockIdx.x * blockDim.x + threadIdx.x;
    if (e >= ET) return;
    int dst = (e < N_EDGES) ? ei[N_EDGES + e] : (e - N_EDGES);
    atomicAdd(&g_deg[dst], 1);
}

// single-kernel chained scan: 49 blocks x 1024; also zeroes g_cursor.
__global__ void csr_scan_kernel() {
    __shared__ int s[1024];
    __shared__ int s_carry;
    int b = blockIdx.x, t = threadIdx.x;
    int i = b * 1024 + t;
    if (i < N_NODES) g_cursor[i] = 0;
    int v = (i < N_NODES) ? g_deg[i] : 0;
    s[t] = v;
    __syncthreads();
#pragma unroll
    for (int off = 1; off < 1024; off <<= 1) {
        int x = (t >= off) ? s[t - off] : 0;
        __syncthreads();
        s[t] += x;
        __syncthreads();
    }
    int incl = s[t];
    int total = s[1023];
    if (t == 0) {
        int carry = 0;
        if (b > 0) {
            while (atomicAdd(&g_flag[b - 1], 0) == 0) { }
            carry = g_carry[b - 1];
        }
        s_carry = carry;
        g_carry[b] = carry + total;
        __threadfence();
        atomicExch(&g_flag[b], 1);
    }
    __syncthreads();
    int carry = s_carry;
    if (i <= N_NODES) g_rowptr[i] = carry + incl - v;   // exclusive prefix
}

__global__ void csr_scatter_kernel(const int* __restrict__ ei) {
    int e = blockIdx.x * blockDim.x + threadIdx.x;
    if (e >= ET) return;
    int src, dst;
    if (e < N_EDGES) { src = ei[e]; dst = ei[N_EDGES + e]; }
    else             { src = dst = e - N_EDGES; }
    int pos = atomicAdd(&g_cursor[dst], 1);
    g_col[g_rowptr[dst] + pos] = src;
}

// ================= register-tiled GEMM: g_h = x @ W =================
// 64 nodes x (32*TN) feats per block, 256 threads, 8x TN micro-tile.
// ft = tid&31 owns feats [ft*TN, ft*TN+TN); nt = tid>>5 owns nodes nt*8..+8.
template <int TN, int FOUT_REAL>
__global__ __launch_bounds__(256) void gemm_tile_kernel(const float* __restrict__ x,
                                                        const float* __restrict__ W) {
    const int FOUT_PAD = 32 * TN;
    __shared__ float ws[32][FOUT_PAD];
    __shared__ float xs[64][36];
    int tid = threadIdx.x;
    int ft = tid & 31;
    int nt = tid >> 5;
    int n0 = blockIdx.x * 64;

    float acc[8][TN];
#pragma unroll
    for (int i = 0; i < 8; i++)
#pragma unroll
        for (int j = 0; j < TN; j++) acc[i][j] = 0.f;

    for (int kt = 0; kt < 128; kt += 32) {
        // x tile: 64x32 = 512 float4 loads
#pragma unroll
        for (int idx = tid; idx < 512; idx += 256) {
            int r = idx >> 3, c4 = idx & 7;
            int n = n0 + r;
            float4 v = (n < N_NODES) ? *(const float4*)&x[n * 128 + kt + c4 * 4]
                                     : make_float4(0.f, 0.f, 0.f, 0.f);
            *(float4*)&xs[r][c4 * 4] = v;
        }
        // W tile: 32 x FOUT_PAD
        const int NF4 = FOUT_PAD / 4;
        for (int idx = tid; idx < 32 * NF4; idx += 256) {
            int r = idx / NF4, c4 = idx % NF4;
            int col = c4 * 4;
            float4 v = (col + 3 < FOUT_REAL)
                           ? *(const float4*)&W[(kt + r) * FOUT_REAL + col]
                           : make_float4(0.f, 0.f, 0.f, 0.f);
            *(float4*)&ws[r][col] = v;
        }
        __syncthreads();
#pragma unroll
        for (int kk = 0; kk < 32; kk++) {
            float xv[8];
#pragma unroll
            for (int i = 0; i < 8; i++) xv[i] = xs[nt * 8 + i][kk];
            float wv[TN];
            if (TN == 4) {
                float4 w4 = *(const float4*)&ws[kk][ft * 4];
                wv[0] = w4.x; wv[1] = w4.y; wv[2] = w4.z; wv[3] = w4.w;
            } else {
#pragma unroll
                for (int j = 0; j < TN; j += 2) {
                    float2 w2 = *(const float2*)&ws[kk][ft * TN + j];
                    wv[j] = w2.x; wv[j + 1] = w2.y;
                }
            }
#pragma unroll
            for (int i = 0; i < 8; i++)
#pragma unroll
                for (int j = 0; j < TN; j++)
                    acc[i][j] = fmaf(xv[i], wv[j], acc[i][j]);
        }
        __syncthreads();
    }
#pragma unroll
    for (int i = 0; i < 8; i++) {
        int n = n0 + nt * 8 + i;
        if (n < N_NODES) {
            if (TN == 4) {
                *(float4*)&g_h[n * FOUT_REAL + ft * 4] =
                    make_float4(acc[i][0], acc[i][1], acc[i][2], acc[i][3]);
            } else {
#pragma unroll
                for (int j = 0; j < TN; j++) {
                    int f = ft * TN + j;
                    if (f < FOUT_REAL) g_h[n * FOUT_REAL + f] = acc[i][j];
                }
            }
        }
    }
}

// ================= attention coefficients (warp per node) =================
__global__ void attn_coef128_kernel(const float* __restrict__ as,
                                    const float* __restrict__ ad) {
    int gtid = blockIdx.x * blockDim.x + threadIdx.x;
    int n = gtid >> 5;
    int lane = gtid & 31;
    if (n >= N_NODES) return;
    float4 v  = *(const float4*)&g_h[n * F12 + 4 * lane];
    float4 a4 = *(const float4*)&as[4 * lane];
    float4 d4 = *(const float4*)&ad[4 * lane];
    float ps = v.x * a4.x + v.y * a4.y + v.z * a4.z + v.w * a4.w;
    float pd = v.x * d4.x + v.y * d4.y + v.z * d4.z + v.w * d4.w;
    ps += __shfl_xor_sync(0xFFFFFFFFu, ps, 1);
    pd += __shfl_xor_sync(0xFFFFFFFFu, pd, 1);
    ps += __shfl_xor_sync(0xFFFFFFFFu, ps, 2);
    pd += __shfl_xor_sync(0xFFFFFFFFu, pd, 2);
    ps += __shfl_xor_sync(0xFFFFFFFFu, ps, 4);
    pd += __shfl_xor_sync(0xFFFFFFFFu, pd, 4);
    if ((lane & 7) == 0) {
        g_asrc[n * HEADS + (lane >> 3)] = ps;
        g_adst[n * HEADS + (lane >> 3)] = pd;
    }
}

__global__ void attn_coef188_kernel(const float* __restrict__ as,
                                    const float* __restrict__ ad) {
    int gtid = blockIdx.x * blockDim.x + threadIdx.x;
    int n = gtid >> 5;
    int lane = gtid & 31;
    if (n >= N_NODES) return;
    float hs[HEADS] = {0.f, 0.f, 0.f, 0.f};
    float hd[HEADS] = {0.f, 0.f, 0.f, 0.f};
#pragma unroll
    for (int k = 0; k < 6; k++) {
        int f = lane + 32 * k;
        if (f < F3) {
            float v = g_h[n * F3 + f];
            int hh = f / NCLS;
            hs[hh] = fmaf(v, as[f], hs[hh]);
            hd[hh] = fmaf(v, ad[f], hd[hh]);
        }
    }
#pragma unroll
    for (int h = 0; h < HEADS; h++) {
#pragma unroll
        for (int o = 16; o > 0; o >>= 1) {
            hs[h] += __shfl_xor_sync(0xFFFFFFFFu, hs[h], o);
            hd[h] += __shfl_xor_sync(0xFFFFFFFFu, hd[h], o);
        }
    }
    if (lane < HEADS) {
        g_asrc[n * HEADS + lane] = hs[lane];
        g_adst[n * HEADS + lane] = hd[lane];
    }
}

// ================= fused softmax + gather-aggregate (no-max) =================
// softmax is shift-invariant; alpha is bounded (|alpha| small), so exp(alpha)
// directly — removes the rescale dependency chain entirely.
// warp per dst node; lane owns feats [4*lane,4*lane+4), head hh = lane>>3.
__global__ void gat_agg128_kernel(const float* __restrict__ bias) {
    int gtid = blockIdx.x * blockDim.x + threadIdx.x;
    int n = gtid >> 5;
    int lane = gtid & 31;
    if (n >= N_NODES) return;
    int beg = g_rowptr[n];
    int deg = g_rowptr[n + 1] - beg;
    int hh = lane >> 3;
    const float4 adst4 = *(const float4*)&g_adst[n * HEADS];
    float adst_h = (hh == 0) ? adst4.x : (hh == 1) ? adst4.y : (hh == 2) ? adst4.z : adst4.w;

    float den = 0.f;
    float4 acc = make_float4(0.f, 0.f, 0.f, 0.f);
#pragma unroll 4
    for (int i = 0; i < deg; i++) {
        int src = g_col[beg + i];
        float4 s4 = *(const float4*)&g_asrc[src * HEADS];   // broadcast across warp
        float a = ((hh == 0) ? s4.x : (hh == 1) ? s4.y : (hh == 2) ? s4.z : s4.w) + adst_h;
        a = (a >= 0.f) ? a : NEG_SLOPE * a;
        float e = __expf(a);
        den += e;
        float4 v = *(const float4*)&g_h[src * F12 + 4 * lane];
        acc.x = fmaf(v.x, e, acc.x);
        acc.y = fmaf(v.y, e, acc.y);
        acc.z = fmaf(v.z, e, acc.z);
        acc.w = fmaf(v.w, e, acc.w);
    }
    float idv = 1.f / den;
    float4 b4 = *(const float4*)&bias[4 * lane];
    float4 o;
    o.x = fmaxf(fmaf(acc.x, idv, b4.x), 0.f);
    o.y = fmaxf(fmaf(acc.y, idv, b4.y), 0.f);
    o.z = fmaxf(fmaf(acc.z, idv, b4.z), 0.f);
    o.w = fmaxf(fmaf(acc.w, idv, b4.w), 0.f);
    *(float4*)&g_buf[n * F12 + 4 * lane] = o;
}

// layer 3 variant: lane owns feats lane+32k (k<6) spanning multiple heads.
__global__ void gat_agg188_kernel() {
    int gtid = blockIdx.x * blockDim.x + threadIdx.x;
    int n = gtid >> 5;
    int lane = gtid & 31;
    if (n >= N_NODES) return;
    int beg = g_rowptr[n];
    int deg = g_rowptr[n + 1] - beg;
    const float4 adst4 = *(const float4*)&g_adst[n * HEADS];

    int hhk[6];
#pragma unroll
    for (int k = 0; k < 6; k++) hhk[k] = (lane + 32 * k) / NCLS;

    float den[HEADS] = {0.f, 0.f, 0.f, 0.f};
    float acc[6] = {0.f, 0.f, 0.f, 0.f, 0.f, 0.f};

#pragma unroll 2
    for (int i = 0; i < deg; i++) {
        int src = g_col[beg + i];
        float4 s4 = *(const float4*)&g_asrc[src * HEADS];
        float e[HEADS];
        {
            float a0 = s4.x + adst4.x; a0 = (a0 >= 0.f) ? a0 : NEG_SLOPE * a0;
            float a1 = s4.y + adst4.y; a1 = (a1 >= 0.f) ? a1 : NEG_SLOPE * a1;
            float a2 = s4.z + adst4.z; a2 = (a2 >= 0.f) ? a2 : NEG_SLOPE * a2;
            float a3 = s4.w + adst4.w; a3 = (a3 >= 0.f) ? a3 : NEG_SLOPE * a3;
            e[0] = __expf(a0); e[1] = __expf(a1); e[2] = __expf(a2); e[3] = __expf(a3);
        }
#pragma unroll
        for (int h = 0; h < HEADS; h++) den[h] += e[h];
        const float* hrow = &g_h[src * F3];
#pragma unroll
        for (int k = 0; k < 6; k++) {
            int f = lane + 32 * k;
            if (f < F3) acc[k] = fmaf(hrow[f], e[hhk[k]], acc[k]);
        }
    }
#pragma unroll
    for (int k = 0; k < 6; k++) {
        int f = lane + 32 * k;
        if (f < F3) g_agg[n * F3 + f] = acc[k] / den[hhk[k]];
    }
}

// ================= finalize layer 3: head mean + bias + log_softmax =================
// tail: re-zero g_deg / g_flag / g_carry for the next call.
__global__ void finalize3_kernel(const float* __restrict__ b3, float* __restrict__ out) {
    int gtid = blockIdx.x * blockDim.x + threadIdx.x;
    if (gtid < N_NODES) g_deg[gtid] = 0;
    if (gtid < 64) { g_flag[gtid] = 0; g_carry[gtid] = 0; }
    int n = gtid >> 5;
    int lane = gtid & 31;
    if (n >= N_NODES) return;
    int c0 = lane, c1 = lane + 32;
    float v0 = -1e30f, v1 = -1e30f;
    const float* row = &g_agg[n * F3];
    if (c0 < NCLS)
        v0 = 0.25f * (row[c0] + row[NCLS + c0] + row[2 * NCLS + c0] + row[3 * NCLS + c0]) + b3[c0];
    if (c1 < NCLS)
        v1 = 0.25f * (row[c1] + row[NCLS + c1] + row[2 * NCLS + c1] + row[3 * NCLS + c1]) + b3[c1];
    float mm = fmaxf(v0, v1);
#pragma unroll
    for (int o = 16; o > 0; o >>= 1) mm = fmaxf(mm, __shfl_xor_sync(0xFFFFFFFFu, mm, o));
    float s = 0.f;
    if (c0 < NCLS) s += expf(v0 - mm);
    if (c1 < NCLS) s += expf(v1 - mm);
#pragma unroll
    for (int o = 16; o > 0; o >>= 1) s += __shfl_xor_sync(0xFFFFFFFFu, s, o);
    float lse = mm + logf(s);
    if (c0 < NCLS) out[n * NCLS + c0] = v0 - lse;
    if (c1 < NCLS) out[n * NCLS + c1] = v1 - lse;
}

// ================= launch =================
extern "C" void kernel_launch(void* const* d_in, const int* in_sizes, int n_in,
                              void* d_out, int out_size) {
    const float* x   = (const float*)d_in[0];
    const int*   ei  = (const int*)d_in[1];   // edge_index is int32 (JAX x64 disabled)
    const float* W1  = (const float*)d_in[2];
    const float* a1s = (const float*)d_in[3];
    const float* a1d = (const float*)d_in[4];
    const float* b1  = (const float*)d_in[5];
    const float* W2  = (const float*)d_in[6];
    const float* a2s = (const float*)d_in[7];
    const float* a2d = (const float*)d_in[8];
    const float* b2  = (const float*)d_in[9];
    const float* W3  = (const float*)d_in[10];
    const float* a3s = (const float*)d_in[11];
    const float* a3d = (const float*)d_in[12];
    const float* b3  = (const float*)d_in[13];
    float* out = (float*)d_out;

    float* g_buf_ptr = nullptr;
    cudaGetSymbolAddress((void**)&g_buf_ptr, g_buf);

    int eb = (ET + 255) / 256;
    int gemm_blocks = (N_NODES + 63) / 64;       // 782
    int wb = (N_NODES * 32 + 255) / 256;

    // CSR build
    csr_hist_kernel<<<eb, 256>>>(ei);                          // launch 0
    csr_scan_kernel<<<49, 1024>>>();                           // launch 1
    csr_scatter_kernel<<<eb, 256>>>(ei);                       // launch 2
    // layer 1
    gemm_tile_kernel<4, 128><<<gemm_blocks, 256>>>(x, W1);     // launch 3 (profiled)
    attn_coef128_kernel<<<wb, 256>>>(a1s, a1d);
    gat_agg128_kernel<<<wb, 256>>>(b1);
    // layer 2
    gemm_tile_kernel<4, 128><<<gemm_blocks, 256>>>(g_buf_ptr, W2);
    attn_coef128_kernel<<<wb, 256>>>(a2s, a2d);
    gat_agg128_kernel<<<wb, 256>>>(b2);
    // layer 3
    gemm_tile_kernel<6, 188><<<gemm_blocks, 256>>>(g_buf_ptr, W3);
    attn_coef188_kernel<<<wb, 256>>>(a3s, a3d);
    gat_agg188_kernel<<<wb, 256>>>();
    finalize3_kernel<<<wb, 256>>>(b3, out);
}

// round 14
// speedup vs baseline: 1.0042x; 1.0012x over previous
#include <cuda_runtime.h>

#define N_NODES 50000
#define N_EDGES 800000
#define ET      (N_EDGES + N_NODES)   // 850000 edges incl self loops
#define HEADS   4
#define F12     128                    // 4*32
#define F3      188                    // 4*47
#define NCLS    47
#define NEG_SLOPE 0.2f

// ---------------- scratch (device globals, no allocation) ----------------
// g_deg/g_flag/g_carry zero at module load; re-zeroed in finalize3 tail.
__device__ float g_h[N_NODES * F3];        // linear output of current layer
__device__ float g_buf[N_NODES * F12];     // activations between layers
__device__ float g_agg[N_NODES * F3];      // layer-3 aggregation (pre-mean)
__device__ float g_asrc[N_NODES * HEADS];
__device__ float g_adst[N_NODES * HEADS];
__device__ int g_deg[N_NODES];
__device__ int g_rowptr[N_NODES + 1];
__device__ int g_cursor[N_NODES];
__device__ int g_col[ET];                  // src node per CSR slot
__device__ int g_carry[64];
__device__ int g_flag[64];

// ================= CSR build =================
__global__ void csr_hist_kernel(const int* __restrict__ ei) {
    int e = blockIdx.x * blockDim.x + threadIdx.x;
    if (e >= ET) return;
    int dst = (e < N_EDGES) ? ei[N_EDGES + e] : (e - N_EDGES);
    atomicAdd(&g_deg[dst], 1);
}

// single-kernel chained scan: 49 blocks x 1024; also zeroes g_cursor.
__global__ void csr_scan_kernel() {
    __shared__ int s[1024];
    __shared__ int s_carry;
    int b = blockIdx.x, t = threadIdx.x;
    int i = b * 1024 + t;
    if (i < N_NODES) g_cursor[i] = 0;
    int v = (i < N_NODES) ? g_deg[i] : 0;
    s[t] = v;
    __syncthreads();
#pragma unroll
    for (int off = 1; off < 1024; off <<= 1) {
        int x = (t >= off) ? s[t - off] : 0;
        __syncthreads();
        s[t] += x;
        __syncthreads();
    }
    int incl = s[t];
    int total = s[1023];
    if (t == 0) {
        int carry = 0;
        if (b > 0) {
            while (atomicAdd(&g_flag[b - 1], 0) == 0) { }
            carry = g_carry[b - 1];
        }
        s_carry = carry;
        g_carry[b] = carry + total;
        __threadfence();
        atomicExch(&g_flag[b], 1);
    }
    __syncthreads();
    int carry = s_carry;
    if (i <= N_NODES) g_rowptr[i] = carry + incl - v;   // exclusive prefix
}

__global__ void csr_scatter_kernel(const int* __restrict__ ei) {
    int e = blockIdx.x * blockDim.x + threadIdx.x;
    if (e >= ET) return;
    int src, dst;
    if (e < N_EDGES) { src = ei[e]; dst = ei[N_EDGES + e]; }
    else             { src = dst = e - N_EDGES; }
    int pos = atomicAdd(&g_cursor[dst], 1);
    g_col[g_rowptr[dst] + pos] = src;
}

// ================= register-tiled GEMM: g_h = x @ W =================
// 64 nodes x (32*TN) feats per block, 256 threads, 8x TN micro-tile.
// ft = tid&31 owns feats [ft*TN, ft*TN+TN); nt = tid>>5 owns nodes nt*8..+8.
template <int TN, int FOUT_REAL>
__global__ __launch_bounds__(256) void gemm_tile_kernel(const float* __restrict__ x,
                                                        const float* __restrict__ W) {
    const int FOUT_PAD = 32 * TN;
    __shared__ float ws[32][FOUT_PAD];
    __shared__ float xs[64][36];
    int tid = threadIdx.x;
    int ft = tid & 31;
    int nt = tid >> 5;
    int n0 = blockIdx.x * 64;

    float acc[8][TN];
#pragma unroll
    for (int i = 0; i < 8; i++)
#pragma unroll
        for (int j = 0; j < TN; j++) acc[i][j] = 0.f;

    for (int kt = 0; kt < 128; kt += 32) {
        // x tile: 64x32 = 512 float4 loads
#pragma unroll
        for (int idx = tid; idx < 512; idx += 256) {
            int r = idx >> 3, c4 = idx & 7;
            int n = n0 + r;
            float4 v = (n < N_NODES) ? *(const float4*)&x[n * 128 + kt + c4 * 4]
                                     : make_float4(0.f, 0.f, 0.f, 0.f);
            *(float4*)&xs[r][c4 * 4] = v;
        }
        // W tile: 32 x FOUT_PAD
        const int NF4 = FOUT_PAD / 4;
        for (int idx = tid; idx < 32 * NF4; idx += 256) {
            int r = idx / NF4, c4 = idx % NF4;
            int col = c4 * 4;
            float4 v = (col + 3 < FOUT_REAL)
                           ? *(const float4*)&W[(kt + r) * FOUT_REAL + col]
                           : make_float4(0.f, 0.f, 0.f, 0.f);
            *(float4*)&ws[r][col] = v;
        }
        __syncthreads();
#pragma unroll
        for (int kk = 0; kk < 32; kk++) {
            float xv[8];
#pragma unroll
            for (int i = 0; i < 8; i++) xv[i] = xs[nt * 8 + i][kk];
            float wv[TN];
            if (TN == 4) {
                float4 w4 = *(const float4*)&ws[kk][ft * 4];
                wv[0] = w4.x; wv[1] = w4.y; wv[2] = w4.z; wv[3] = w4.w;
            } else {
#pragma unroll
                for (int j = 0; j < TN; j += 2) {
                    float2 w2 = *(const float2*)&ws[kk][ft * TN + j];
                    wv[j] = w2.x; wv[j + 1] = w2.y;
                }
            }
#pragma unroll
            for (int i = 0; i < 8; i++)
#pragma unroll
                for (int j = 0; j < TN; j++)
                    acc[i][j] = fmaf(xv[i], wv[j], acc[i][j]);
        }
        __syncthreads();
    }
#pragma unroll
    for (int i = 0; i < 8; i++) {
        int n = n0 + nt * 8 + i;
        if (n < N_NODES) {
            if (TN == 4) {
                *(float4*)&g_h[n * FOUT_REAL + ft * 4] =
                    make_float4(acc[i][0], acc[i][1], acc[i][2], acc[i][3]);
            } else {
#pragma unroll
                for (int j = 0; j < TN; j++) {
                    int f = ft * TN + j;
                    if (f < FOUT_REAL) g_h[n * FOUT_REAL + f] = acc[i][j];
                }
            }
        }
    }
}

// ================= attention coefficients (warp per node) =================
__global__ void attn_coef128_kernel(const float* __restrict__ as,
                                    const float* __restrict__ ad) {
    int gtid = blockIdx.x * blockDim.x + threadIdx.x;
    int n = gtid >> 5;
    int lane = gtid & 31;
    if (n >= N_NODES) return;
    float4 v  = *(const float4*)&g_h[n * F12 + 4 * lane];
    float4 a4 = *(const float4*)&as[4 * lane];
    float4 d4 = *(const float4*)&ad[4 * lane];
    float ps = v.x * a4.x + v.y * a4.y + v.z * a4.z + v.w * a4.w;
    float pd = v.x * d4.x + v.y * d4.y + v.z * d4.z + v.w * d4.w;
    ps += __shfl_xor_sync(0xFFFFFFFFu, ps, 1);
    pd += __shfl_xor_sync(0xFFFFFFFFu, pd, 1);
    ps += __shfl_xor_sync(0xFFFFFFFFu, ps, 2);
    pd += __shfl_xor_sync(0xFFFFFFFFu, pd, 2);
    ps += __shfl_xor_sync(0xFFFFFFFFu, ps, 4);
    pd += __shfl_xor_sync(0xFFFFFFFFu, pd, 4);
    if ((lane & 7) == 0) {
        g_asrc[n * HEADS + (lane >> 3)] = ps;
        g_adst[n * HEADS + (lane >> 3)] = pd;
    }
}

__global__ void attn_coef188_kernel(const float* __restrict__ as,
                                    const float* __restrict__ ad) {
    int gtid = blockIdx.x * blockDim.x + threadIdx.x;
    int n = gtid >> 5;
    int lane = gtid & 31;
    if (n >= N_NODES) return;
    float hs[HEADS] = {0.f, 0.f, 0.f, 0.f};
    float hd[HEADS] = {0.f, 0.f, 0.f, 0.f};
#pragma unroll
    for (int k = 0; k < 6; k++) {
        int f = lane + 32 * k;
        if (f < F3) {
            float v = g_h[n * F3 + f];
            int hh = f / NCLS;
            hs[hh] = fmaf(v, as[f], hs[hh]);
            hd[hh] = fmaf(v, ad[f], hd[hh]);
        }
    }
#pragma unroll
    for (int h = 0; h < HEADS; h++) {
#pragma unroll
        for (int o = 16; o > 0; o >>= 1) {
            hs[h] += __shfl_xor_sync(0xFFFFFFFFu, hs[h], o);
            hd[h] += __shfl_xor_sync(0xFFFFFFFFu, hd[h], o);
        }
    }
    if (lane < HEADS) {
        g_asrc[n * HEADS + lane] = hs[lane];
        g_adst[n * HEADS + lane] = hd[lane];
    }
}

// ================= fused softmax + gather-aggregate (no-max) =================
// softmax is shift-invariant; alpha is bounded (|alpha| small), so exp(alpha)
// directly — removes the rescale dependency chain entirely.
// warp per dst node; lane owns feats [4*lane,4*lane+4), head hh = lane>>3.
__global__ void gat_agg128_kernel(const float* __restrict__ bias) {
    int gtid = blockIdx.x * blockDim.x + threadIdx.x;
    int n = gtid >> 5;
    int lane = gtid & 31;
    if (n >= N_NODES) return;
    int beg = g_rowptr[n];
    int deg = g_rowptr[n + 1] - beg;
    int hh = lane >> 3;
    const float4 adst4 = *(const float4*)&g_adst[n * HEADS];
    float adst_h = (hh == 0) ? adst4.x : (hh == 1) ? adst4.y : (hh == 2) ? adst4.z : adst4.w;

    float den = 0.f;
    float4 acc = make_float4(0.f, 0.f, 0.f, 0.f);
#pragma unroll 4
    for (int i = 0; i < deg; i++) {
        int src = g_col[beg + i];
        float4 s4 = *(const float4*)&g_asrc[src * HEADS];   // broadcast across warp
        float a = ((hh == 0) ? s4.x : (hh == 1) ? s4.y : (hh == 2) ? s4.z : s4.w) + adst_h;
        a = (a >= 0.f) ? a : NEG_SLOPE * a;
        float e = __expf(a);
        den += e;
        float4 v = *(const float4*)&g_h[src * F12 + 4 * lane];
        acc.x = fmaf(v.x, e, acc.x);
        acc.y = fmaf(v.y, e, acc.y);
        acc.z = fmaf(v.z, e, acc.z);
        acc.w = fmaf(v.w, e, acc.w);
    }
    float idv = 1.f / den;
    float4 b4 = *(const float4*)&bias[4 * lane];
    float4 o;
    o.x = fmaxf(fmaf(acc.x, idv, b4.x), 0.f);
    o.y = fmaxf(fmaf(acc.y, idv, b4.y), 0.f);
    o.z = fmaxf(fmaf(acc.z, idv, b4.z), 0.f);
    o.w = fmaxf(fmaf(acc.w, idv, b4.w), 0.f);
    *(float4*)&g_buf[n * F12 + 4 * lane] = o;
}

// layer 3 variant: lane owns feats lane+32k (k<6) spanning multiple heads.
__global__ void gat_agg188_kernel() {
    int gtid = blockIdx.x * blockDim.x + threadIdx.x;
    int n = gtid >> 5;
    int lane = gtid & 31;
    if (n >= N_NODES) return;
    int beg = g_rowptr[n];
    int deg = g_rowptr[n + 1] - beg;
    const float4 adst4 = *(const float4*)&g_adst[n * HEADS];

    int hhk[6];
#pragma unroll
    for (int k = 0; k < 6; k++) hhk[k] = (lane + 32 * k) / NCLS;

    float den[HEADS] = {0.f, 0.f, 0.f, 0.f};
    float acc[6] = {0.f, 0.f, 0.f, 0.f, 0.f, 0.f};

#pragma unroll 2
    for (int i = 0; i < deg; i++) {
        int src = g_col[beg + i];
        float4 s4 = *(const float4*)&g_asrc[src * HEADS];
        float e[HEADS];
        {
            float a0 = s4.x + adst4.x; a0 = (a0 >= 0.f) ? a0 : NEG_SLOPE * a0;
            float a1 = s4.y + adst4.y; a1 = (a1 >= 0.f) ? a1 : NEG_SLOPE * a1;
            float a2 = s4.z + adst4.z; a2 = (a2 >= 0.f) ? a2 : NEG_SLOPE * a2;
            float a3 = s4.w + adst4.w; a3 = (a3 >= 0.f) ? a3 : NEG_SLOPE * a3;
            e[0] = __expf(a0); e[1] = __expf(a1); e[2] = __expf(a2); e[3] = __expf(a3);
        }
#pragma unroll
        for (int h = 0; h < HEADS; h++) den[h] += e[h];
        const float* hrow = &g_h[src * F3];
#pragma unroll
        for (int k = 0; k < 6; k++) {
            int f = lane + 32 * k;
            if (f < F3) acc[k] = fmaf(hrow[f], e[hhk[k]], acc[k]);
        }
    }
#pragma unroll
    for (int k = 0; k < 6; k++) {
        int f = lane + 32 * k;
        if (f < F3) g_agg[n * F3 + f] = acc[k] / den[hhk[k]];
    }
}

// ================= finalize layer 3: head mean + bias + log_softmax =================
// tail: re-zero g_deg / g_flag / g_carry for the next call.
__global__ void finalize3_kernel(const float* __restrict__ b3, float* __restrict__ out) {
    int gtid = blockIdx.x * blockDim.x + threadIdx.x;
    if (gtid < N_NODES) g_deg[gtid] = 0;
    if (gtid < 64) { g_flag[gtid] = 0; g_carry[gtid] = 0; }
    int n = gtid >> 5;
    int lane = gtid & 31;
    if (n >= N_NODES) return;
    int c0 = lane, c1 = lane + 32;
    float v0 = -1e30f, v1 = -1e30f;
    const float* row = &g_agg[n * F3];
    if (c0 < NCLS)
        v0 = 0.25f * (row[c0] + row[NCLS + c0] + row[2 * NCLS + c0] + row[3 * NCLS + c0]) + b3[c0];
    if (c1 < NCLS)
        v1 = 0.25f * (row[c1] + row[NCLS + c1] + row[2 * NCLS + c1] + row[3 * NCLS + c1]) + b3[c1];
    float mm = fmaxf(v0, v1);
#pragma unroll
    for (int o = 16; o > 0; o >>= 1) mm = fmaxf(mm, __shfl_xor_sync(0xFFFFFFFFu, mm, o));
    float s = 0.f;
    if (c0 < NCLS) s += expf(v0 - mm);
    if (c1 < NCLS) s += expf(v1 - mm);
#pragma unroll
    for (int o = 16; o > 0; o >>= 1) s += __shfl_xor_sync(0xFFFFFFFFu, s, o);
    float lse = mm + logf(s);
    if (c0 < NCLS) out[n * NCLS + c0] = v0 - lse;
    if (c1 < NCLS) out[n * NCLS + c1] = v1 - lse;
}

// ================= launch =================
extern "C" void kernel_launch(void* const* d_in, const int* in_sizes, int n_in,
                              void* d_out, int out_size) {
    const float* x   = (const float*)d_in[0];
    const int*   ei  = (const int*)d_in[1];   // edge_index is int32 (JAX x64 disabled)
    const float* W1  = (const float*)d_in[2];
    const float* a1s = (const float*)d_in[3];
    const float* a1d = (const float*)d_in[4];
    const float* b1  = (const float*)d_in[5];
    const float* W2  = (const float*)d_in[6];
    const float* a2s = (const float*)d_in[7];
    const float* a2d = (const float*)d_in[8];
    const float* b2  = (const float*)d_in[9];
    const float* W3  = (const float*)d_in[10];
    const float* a3s = (const float*)d_in[11];
    const float* a3d = (const float*)d_in[12];
    const float* b3  = (const float*)d_in[13];
    float* out = (float*)d_out;

    float* g_buf_ptr = nullptr;
    cudaGetSymbolAddress((void**)&g_buf_ptr, g_buf);

    int eb = (ET + 255) / 256;
    int gemm_blocks = (N_NODES + 63) / 64;       // 782
    int wb = (N_NODES * 32 + 255) / 256;

    // CSR build
    csr_hist_kernel<<<eb, 256>>>(ei);                          // launch 0
    csr_scan_kernel<<<49, 1024>>>();                           // launch 1
    csr_scatter_kernel<<<eb, 256>>>(ei);                       // launch 2
    // layer 1
    gemm_tile_kernel<4, 128><<<gemm_blocks, 256>>>(x, W1);     // launch 3 (profiled)
    attn_coef128_kernel<<<wb, 256>>>(a1s, a1d);
    gat_agg128_kernel<<<wb, 256>>>(b1);
    // layer 2
    gemm_tile_kernel<4, 128><<<gemm_blocks, 256>>>(g_buf_ptr, W2);
    attn_coef128_kernel<<<wb, 256>>>(a2s, a2d);
    gat_agg128_kernel<<<wb, 256>>>(b2);
    // layer 3
    gemm_tile_kernel<6, 188><<<gemm_blocks, 256>>>(g_buf_ptr, W3);
    attn_coef188_kernel<<<wb, 256>>>(a3s, a3d);
    gat_agg188_kernel<<<wb, 256>>>();
    finalize3_kernel<<<wb, 256>>>(b3, out);
}